// round 15
// baseline (speedup 1.0000x reference)
#include <cuda_runtime.h>
#include <cuda_bf16.h>
#include <math.h>

#define BATCH   512
#define T_STEPS 512
#define CHAN    32
#define CIN     33
#define HID     128
#define GATES   512   // 4*H
#define EPSF    1e-12f

#define KREG    24    // k2-pairs held in registers (48 regs)
#define KSMEM   (HID / 2 - KREG)   // 40 k2-pairs in smem
#define K4SMEM  (KSMEM / 2)        // 20 k4 groups in smem

typedef unsigned long long ull_t;
typedef unsigned int u32_t;

// ---------------------------------------------------------------------------
// f32x2 packed-math helpers (Blackwell FFMA2 path — only reachable via PTX)
// ---------------------------------------------------------------------------
__device__ __forceinline__ void ffma2(ull_t& d, ull_t a, ull_t b) {
    asm("fma.rn.f32x2 %0, %1, %2, %0;" : "+l"(d) : "l"(a), "l"(b));
}
__device__ __forceinline__ ull_t pack_dup(float v) {
    ull_t r; u32_t b = __float_as_uint(v);
    asm("mov.b64 %0, {%1, %1};" : "=l"(r) : "r"(b));
    return r;
}
__device__ __forceinline__ float2 unpack2(ull_t d) {
    u32_t lo, hi;
    asm("mov.b64 {%0, %1}, %2;" : "=r"(lo), "=r"(hi) : "l"(d));
    return make_float2(__uint_as_float(lo), __uint_as_float(hi));
}
__device__ __forceinline__ float hsum2(ull_t d) {
    float2 f = unpack2(d); return f.x + f.y;
}
__device__ __forceinline__ ull_t pack2(float a, float b) {
    ull_t r;
    asm("mov.b64 %0, {%1, %2};" : "=l"(r)
        : "r"(__float_as_uint(a)), "r"(__float_as_uint(b)));
    return r;
}

// ---------------------------------------------------------------------------
// Device scratch (static; allocations are forbidden)
// ---------------------------------------------------------------------------
__device__ float g_std_arr[T_STEPS];             // minibatch-std scalar per t
__device__ float g_inv_arr[4];                   // 1/sigma: ih, hh, fc
__device__ float g_wt[CIN * GATES];              // Wih^T scaled: [33][512]
__device__ float g_bias[GATES];                  // b_ih + b_hh
__device__ ull_t g_whh_f[(HID / 2) * GATES];     // f32 k-pairs, k2-major [64][512]
__device__ float g_gates[(size_t)BATCH * T_STEPS * GATES]; // 536 MB gates_x

// ---------------------------------------------------------------------------
// Kernel A: minibatch std feature. grid=T, block=256 (8 b-seg x 32 chan)
// ---------------------------------------------------------------------------
__global__ void std_kernel(const float* __restrict__ x)
{
    int t   = blockIdx.x;
    int tid = threadIdx.x;
    int c   = tid & 31;
    int seg = tid >> 5;

    float s = 0.f, ss = 0.f;
    for (int b = seg; b < BATCH; b += 8) {
        float v = x[((size_t)b * T_STEPS + t) * CHAN + c];
        s  += v;
        ss += v * v;
    }
    __shared__ float sm1[256], sm2[256];
    sm1[tid] = s; sm2[tid] = ss;
    __syncthreads();
    if (seg == 0) {
        for (int k = 1; k < 8; k++) { s += sm1[k * 32 + c]; ss += sm2[k * 32 + c]; }
        float mean = s * (1.f / 512.f);
        float var  = (ss - 512.f * mean * mean) * (1.f / 511.f);
        float sd   = sqrtf(fmaxf(var, 0.f));
        #pragma unroll
        for (int off = 16; off; off >>= 1)
            sd += __shfl_xor_sync(0xffffffffu, sd, off);
        if (c == 0) g_std_arr[t] = sd * (1.f / 32.f);
    }
}

// ---------------------------------------------------------------------------
// Kernel B: spectral norms (one power iteration, matching reference exactly)
// then scale+transpose Wih, combine bias, pack Whh as f32 k-pairs.
// single block, 512 threads
// ---------------------------------------------------------------------------
__global__ void prep_kernel(const float* __restrict__ wih, const float* __restrict__ uih,
                            const float* __restrict__ whh, const float* __restrict__ uhh,
                            const float* __restrict__ bih, const float* __restrict__ bhh,
                            const float* __restrict__ wfc, const float* __restrict__ ufc)
{
    __shared__ float tv[HID];
    __shared__ float red[512];
    __shared__ float nrm;
    __shared__ float inv_s[4];
    int tid = threadIdx.x;

    // ---- ih: W [512,33] ----
    if (tid < CIN) {
        float s = 0.f;
        for (int g = 0; g < GATES; g++) s += wih[g * CIN + tid] * uih[g];
        tv[tid] = s;
    }
    __syncthreads();
    if (tid == 0) {
        float n = 0.f;
        for (int c = 0; c < CIN; c++) n += tv[c] * tv[c];
        nrm = sqrtf(n) + EPSF;
    }
    __syncthreads();
    {
        float a = 0.f;
        for (int c = 0; c < CIN; c++) a += wih[tid * CIN + c] * tv[c];
        a /= nrm;
        red[tid] = a * a;
    }
    __syncthreads();
    for (int off = 256; off; off >>= 1) {
        if (tid < off) red[tid] += red[tid + off];
        __syncthreads();
    }
    if (tid == 0) {
        float ssum = red[0];                      // ||W v||^2
        float v = (sqrtf(ssum) + EPSF) / ssum;    // 1/sigma
        g_inv_arr[0] = v; inv_s[0] = v;
    }
    __syncthreads();

    // ---- hh: W [512,128] ----
    if (tid < HID) {
        float s = 0.f;
        for (int g = 0; g < GATES; g++) s += whh[g * HID + tid] * uhh[g];
        tv[tid] = s;
    }
    __syncthreads();
    if (tid == 0) {
        float n = 0.f;
        for (int k = 0; k < HID; k++) n += tv[k] * tv[k];
        nrm = sqrtf(n) + EPSF;
    }
    __syncthreads();
    {
        float a = 0.f;
        for (int k = 0; k < HID; k++) a += whh[tid * HID + k] * tv[k];
        a /= nrm;
        red[tid] = a * a;
    }
    __syncthreads();
    for (int off = 256; off; off >>= 1) {
        if (tid < off) red[tid] += red[tid + off];
        __syncthreads();
    }
    if (tid == 0) {
        float ssum = red[0];
        float v = (sqrtf(ssum) + EPSF) / ssum;
        g_inv_arr[1] = v; inv_s[1] = v;
    }
    __syncthreads();

    // ---- fc: W [1,128] ----
    red[tid] = (tid < HID) ? wfc[tid] * wfc[tid] : 0.f;
    __syncthreads();
    for (int off = 256; off; off >>= 1) {
        if (tid < off) red[tid] += red[tid + off];
        __syncthreads();
    }
    if (tid == 0) {
        float wn2 = red[0];
        float u0  = ufc[0];
        float tn  = fabsf(u0) * sqrtf(wn2) + EPSF;   // ||W^T u||
        float s   = u0 * wn2 / tn;                   // W @ v (scalar)
        float sig = s * s / (fabsf(s) + EPSF);
        float v = 1.f / sig;
        g_inv_arr[2] = v; inv_s[2] = v;
    }
    __syncthreads();

    // ---- scale + pack ----
    float i0 = inv_s[0], i1 = inv_s[1];
    // Wih transposed & scaled: g_wt[c*512+g]
    for (int c = 0; c < CIN; c++)
        g_wt[c * GATES + tid] = wih[tid * CIN + c] * i0;
    g_bias[tid] = bih[tid] + bhh[tid];
    // Whh scaled -> f32 k-pairs, k2-major: g_whh_f[k2*512 + g]
    for (int k2 = 0; k2 < HID / 2; k2++) {
        float we = whh[tid * HID + 2 * k2]     * i1;
        float wo = whh[tid * HID + 2 * k2 + 1] * i1;
        g_whh_f[k2 * GATES + tid] = pack2(we, wo);
    }
}

// ---------------------------------------------------------------------------
// Kernel C: gates_x = x_aug @ Wih_n^T + bias (f32x2 packed over gate pairs).
// grid = 8192 blocks x 32 rows, 256 threads; thread t owns gates (2t, 2t+1).
// ---------------------------------------------------------------------------
__global__ void gates_kernel(const float* __restrict__ x)
{
    __shared__ ull_t xs_d[CIN * 34];   // x duplicated (v,v), [c][34 rows]
    int row0 = blockIdx.x * 32;
    int tid  = threadIdx.x;

    for (int i = tid; i < 32 * CHAN; i += 256) {
        int r = i >> 5, c = i & 31;
        xs_d[c * 34 + r] = pack_dup(x[(size_t)(row0 + r) * CHAN + c]);
    }
    if (tid < 32)
        xs_d[CHAN * 34 + tid] = pack_dup(g_std_arr[(row0 + tid) & (T_STEPS - 1)]);
    __syncthreads();

    const ull_t* wt2   = (const ull_t*)g_wt;     // (w_2t, w_2t+1) f32 pairs
    const ull_t* bias2 = (const ull_t*)g_bias;
    ull_t*       gout  = (ull_t*)g_gates;
    ull_t bp = bias2[tid];

    for (int rb = 0; rb < 32; rb += 8) {
        ull_t acc[8];
        #pragma unroll
        for (int r = 0; r < 8; r++) acc[r] = bp;
        #pragma unroll
        for (int c = 0; c < CIN; c++) {
            ull_t w = wt2[c * (GATES / 2) + tid];
            #pragma unroll
            for (int r = 0; r < 8; r++)
                ffma2(acc[r], w, xs_d[c * 34 + rb + r]);
        }
        #pragma unroll
        for (int r = 0; r < 8; r++)
            gout[(size_t)(row0 + rb + r) * (GATES / 2) + tid] = acc[r];
    }
}

// ---------------------------------------------------------------------------
// Kernel D: persistent LSTM + online-softmax attention + FC epilogue.
// 128 blocks x 4 batch rows, 512 THREADS (4 warps/SMSP), 512 steps.
// Thread t owns gate g=t for all 4 rows. Weights f32x2 (no unpack):
// k2 0..23 in 48 regs, k2 24..63 in 160 KB smem (ull2 per k4, LDS.128).
// Pointwise 1 slot/thread; softmax state in regs; two barriers/step.
// ---------------------------------------------------------------------------
__global__ void __launch_bounds__(512, 1)
lstm_kernel(const float* __restrict__ attn_w,
            const float* __restrict__ fc_w,
            const float* __restrict__ fc_b,
            float* __restrict__ out)
{
    extern __shared__ __align__(16) unsigned char smem_raw[];
    ulonglong2* wsm2 = (ulonglong2*)smem_raw;      // [20 k4][512]: {pair(2k4), pair(2k4+1)}

    __shared__ __align__(16) float h_s[4 * HID];   // [4][128]
    __shared__ float gts[4 * GATES];               // [4][512]
    __shared__ float aw_s[HID];
    __shared__ float fw_s[HID];
    __shared__ float lpart[16];                    // per-warp attn partials

    int tid  = threadIdx.x;
    int b0   = blockIdx.x * 4;
    int wid  = tid >> 5, lane = tid & 31;
    int r0   = tid >> 7;          // pointwise row (0..3)
    int j0   = tid & 127;         // hidden index

    const ull_t* gwf = (const ull_t*)g_whh_f;      // [64 k2][512 g] f32 pairs

    // weights: k2 0..KREG-1 into registers (48 regs), rest staged into smem
    ull_t wreg[KREG];
    #pragma unroll
    for (int k2 = 0; k2 < KREG; k2++)
        wreg[k2] = gwf[k2 * GATES + tid];
    for (int i = tid; i < K4SMEM * GATES; i += 512) {
        int k4l = i >> 9, g = i & 511;             // local k4 -> global k2 = KREG+2*k4l
        ulonglong2 v;
        v.x = gwf[(KREG + 2 * k4l)     * GATES + g];
        v.y = gwf[(KREG + 2 * k4l + 1) * GATES + g];
        wsm2[i] = v;
    }

    if (tid < 4 * HID) h_s[tid] = 0.f;
    if (tid < HID) { aw_s[tid] = attn_w[tid]; fw_s[tid] = fc_w[tid]; }
    __syncthreads();

    float cst  = 0.f;          // cell state for slot (r0, j0)
    float accp = 0.f;          // online pooled accumulator
    float mloc = -INFINITY;    // softmax running max (redundant per row-thread)
    float sloc = 0.f;          // softmax running sum

    const float4* h4   = (const float4*)h_s;       // [4][32] float4 (k4-granular)
    const float*  gsrc = g_gates;

    for (int t = 0; t < T_STEPS; t++) {
        // prefetch gates_x (coalesced; latency hidden under the matvec)
        float gx[4];
        #pragma unroll
        for (int r = 0; r < 4; r++)
            gx[r] = gsrc[((size_t)(b0 + r) * T_STEPS + t) * GATES + tid];

        // gates += h @ Whh^T  (acc = (sum_even_k, sum_odd_k) per gate)
        ull_t a[4] = {0, 0, 0, 0};
        #pragma unroll
        for (int k4 = 0; k4 < KREG / 2; k4++) {     // register half (no unpack!)
            ull_t wA = wreg[2 * k4];                // k2 = 2k4
            ull_t wB = wreg[2 * k4 + 1];            // k2 = 2k4+1
            #pragma unroll
            for (int r = 0; r < 4; r++) {
                float4 hv = h4[r * (HID / 4) + k4]; // LDS.128 broadcast
                ffma2(a[r], wA, pack2(hv.x, hv.y));
                ffma2(a[r], wB, pack2(hv.z, hv.w));
            }
        }
        #pragma unroll 10
        for (int k4 = KREG / 2; k4 < HID / 4; k4++) {  // smem half
            ulonglong2 wp = wsm2[(k4 - KREG / 2) * GATES + tid];   // LDS.128
            #pragma unroll
            for (int r = 0; r < 4; r++) {
                float4 hv = h4[r * (HID / 4) + k4];
                ffma2(a[r], wp.x, pack2(hv.x, hv.y));
                ffma2(a[r], wp.y, pack2(hv.z, hv.w));
            }
        }
        #pragma unroll
        for (int r = 0; r < 4; r++)
            gts[r * GATES + tid] = hsum2(a[r]) + gx[r];
        __syncthreads();                            // sync1: gates ready

        // pointwise LSTM cell (1 slot/thread); exp-based activations
        const float* gr = &gts[r0 * GATES];
        float gi = gr[j0], gf = gr[HID + j0];
        float gg = gr[2 * HID + j0], go = gr[3 * HID + j0];
        float iv = 1.f / (1.f + __expf(-gi));
        float fv = 1.f / (1.f + __expf(-gf));
        float gv = 2.f / (1.f + __expf(-2.f * gg)) - 1.f;   // tanh
        float ov = 1.f / (1.f + __expf(-go));
        float c  = fv * cst + iv * gv;
        cst      = c;
        float hv = ov * (2.f / (1.f + __expf(-2.f * c)) - 1.f);
        h_s[r0 * HID + j0] = hv;

        // attention partial: per-warp shuffle reduce of h*aw
        float part = hv * aw_s[j0];
        #pragma unroll
        for (int off = 16; off; off >>= 1)
            part += __shfl_xor_sync(0xffffffffu, part, off);
        if (lane == 0) lpart[wid] = part;
        __syncthreads();                            // sync2: h + partials ready

        // online softmax, state in registers (redundant across a row's threads)
        float l = lpart[r0 * 4] + lpart[r0 * 4 + 1]
                + lpart[r0 * 4 + 2] + lpart[r0 * 4 + 3];
        float mnew = fmaxf(mloc, l);
        float al   = __expf(mloc - mnew);           // 0 on first step
        float pv   = __expf(l - mnew);
        mloc = mnew;
        sloc = sloc * al + pv;
        accp = accp * al + pv * hv;
        // hazards: h_s written pre-sync2, read by matvec(t+1) post-sync2 ✓;
        // gts read pre-sync2, rewritten post-sync2 ✓; lpart read here post-
        // sync2, next written post-sync1(t+1) ✓. Two barriers/step suffice.
    }

    // epilogue: pooled = acc/s ; score = pooled . (fc_w/sigma) + fc_b
    __syncthreads();                                // lpart reads done, reuse
    float po   = accp / sloc;
    float part = po * fw_s[j0];
    #pragma unroll
    for (int off = 16; off; off >>= 1)
        part += __shfl_xor_sync(0xffffffffu, part, off);
    if (lane == 0) lpart[wid] = part;
    __syncthreads();
    if (tid < 4) {
        float sc = lpart[tid * 4] + lpart[tid * 4 + 1]
                 + lpart[tid * 4 + 2] + lpart[tid * 4 + 3];
        out[b0 + tid] = sc * g_inv_arr[2] + fc_b[0];
    }
}

// ---------------------------------------------------------------------------
extern "C" void kernel_launch(void* const* d_in, const int* in_sizes, int n_in,
                              void* d_out, int out_size)
{
    const float* x      = (const float*)d_in[0];
    const float* w_ih   = (const float*)d_in[1];
    const float* u_ih   = (const float*)d_in[2];
    const float* w_hh   = (const float*)d_in[3];
    const float* u_hh   = (const float*)d_in[4];
    const float* b_ih   = (const float*)d_in[5];
    const float* b_hh   = (const float*)d_in[6];
    const float* attn_w = (const float*)d_in[7];
    // d_in[8] = attn_b (softmax shift-invariant, unused)
    const float* fc_w   = (const float*)d_in[9];
    const float* u_fc   = (const float*)d_in[10];
    const float* fc_b   = (const float*)d_in[11];
    float* out = (float*)d_out;

    std_kernel<<<T_STEPS, 256>>>(x);
    prep_kernel<<<1, 512>>>(w_ih, u_ih, w_hh, u_hh, b_ih, b_hh, fc_w, u_fc);
    gates_kernel<<<(BATCH * T_STEPS) / 32, 256>>>(x);

    int smem = K4SMEM * GATES * 16;   // 160 KB dynamic: smem weight half (ull2)
    cudaFuncSetAttribute(lstm_kernel, cudaFuncAttributeMaxDynamicSharedMemorySize, smem);
    lstm_kernel<<<BATCH / 4, 512, smem>>>(attn_w, fc_w, fc_b, out);
}

// round 16
// speedup vs baseline: 1.1830x; 1.1830x over previous
#include <cuda_runtime.h>
#include <cuda_bf16.h>
#include <math.h>

#define BATCH   512
#define T_STEPS 512
#define CHAN    32
#define CIN     33
#define HID     128
#define GATES   512   // 4*H
#define EPSF    1e-12f

#define KREG2   8                     // k2-pairs (k 0..15) in f32 registers
#define K4SM    ((HID / 4) - KREG2 / 2)  // 28 k4 groups (k 16..127) in smem, bf16
#define HPAD    132                   // padded h row stride (floats)

typedef unsigned long long ull_t;
typedef unsigned int u32_t;

// ---------------------------------------------------------------------------
// f32x2 packed-math helpers (Blackwell FFMA2 path — only reachable via PTX)
// ---------------------------------------------------------------------------
__device__ __forceinline__ void ffma2(ull_t& d, ull_t a, ull_t b) {
    asm("fma.rn.f32x2 %0, %1, %2, %0;" : "+l"(d) : "l"(a), "l"(b));
}
// (bf16_lo, bf16_hi) packed in u32 -> (f32_lo, f32_hi) packed b64 (pure ALU)
__device__ __forceinline__ ull_t bf2_to_f32x2(u32_t u) {
    ull_t r;
    asm("{\n\t.reg .b32 lo, hi;\n\t"
        "shl.b32 lo, %1, 16;\n\t"
        "and.b32 hi, %1, 0xFFFF0000;\n\t"
        "mov.b64 %0, {lo, hi};\n\t}" : "=l"(r) : "r"(u));
    return r;
}
__device__ __forceinline__ ull_t pack_dup(float v) {
    ull_t r; u32_t b = __float_as_uint(v);
    asm("mov.b64 %0, {%1, %1};" : "=l"(r) : "r"(b));
    return r;
}
__device__ __forceinline__ float2 unpack2(ull_t d) {
    u32_t lo, hi;
    asm("mov.b64 {%0, %1}, %2;" : "=r"(lo), "=r"(hi) : "l"(d));
    return make_float2(__uint_as_float(lo), __uint_as_float(hi));
}
__device__ __forceinline__ float hsum2(ull_t d) {
    float2 f = unpack2(d); return f.x + f.y;
}
__device__ __forceinline__ u32_t pack_bf2(float a, float b) {
    u32_t ua = (u32_t)__bfloat16_as_ushort(__float2bfloat16(a));
    u32_t ub = (u32_t)__bfloat16_as_ushort(__float2bfloat16(b));
    return ua | (ub << 16);
}
__device__ __forceinline__ ull_t pack2(float a, float b) {
    ull_t r;
    asm("mov.b64 %0, {%1, %2};" : "=l"(r)
        : "r"(__float_as_uint(a)), "r"(__float_as_uint(b)));
    return r;
}

// ---------------------------------------------------------------------------
// Device scratch (static; allocations are forbidden)
// ---------------------------------------------------------------------------
__device__ float g_std_arr[T_STEPS];             // minibatch-std scalar per t
__device__ float g_inv_arr[4];                   // 1/sigma: ih, hh, fc
__device__ float g_wt[CIN * GATES];              // Wih^T scaled: [33][512]
__device__ float g_bias[GATES];                  // b_ih + b_hh
// register half: [8 k2][256 gp] {wE f32-pair, wO f32-pair}
__device__ ulonglong2 g_whh_r[KREG2 * 256];
// smem half (bf16): [28 k4][256 gp] {pairE_a|pairO_a<<32, pairE_b|pairO_b<<32}
__device__ ulonglong2 g_whh_s[K4SM * 256];
__device__ float g_gates[(size_t)BATCH * T_STEPS * GATES]; // 536 MB gates_x

// ---------------------------------------------------------------------------
// Kernel A: minibatch std feature. grid=T, block=256 (8 b-seg x 32 chan)
// ---------------------------------------------------------------------------
__global__ void std_kernel(const float* __restrict__ x)
{
    int t   = blockIdx.x;
    int tid = threadIdx.x;
    int c   = tid & 31;
    int seg = tid >> 5;

    float s = 0.f, ss = 0.f;
    for (int b = seg; b < BATCH; b += 8) {
        float v = x[((size_t)b * T_STEPS + t) * CHAN + c];
        s  += v;
        ss += v * v;
    }
    __shared__ float sm1[256], sm2[256];
    sm1[tid] = s; sm2[tid] = ss;
    __syncthreads();
    if (seg == 0) {
        for (int k = 1; k < 8; k++) { s += sm1[k * 32 + c]; ss += sm2[k * 32 + c]; }
        float mean = s * (1.f / 512.f);
        float var  = (ss - 512.f * mean * mean) * (1.f / 511.f);
        float sd   = sqrtf(fmaxf(var, 0.f));
        #pragma unroll
        for (int off = 16; off; off >>= 1)
            sd += __shfl_xor_sync(0xffffffffu, sd, off);
        if (c == 0) g_std_arr[t] = sd * (1.f / 32.f);
    }
}

// ---------------------------------------------------------------------------
// Kernel B: spectral norms (one power iteration, matching reference exactly)
// then scale+transpose Wih, combine bias, pack Whh (f32 reg half + bf16 smem
// half, gate-paired layout). single block, 512 threads (tid = gate).
// ---------------------------------------------------------------------------
__global__ void prep_kernel(const float* __restrict__ wih, const float* __restrict__ uih,
                            const float* __restrict__ whh, const float* __restrict__ uhh,
                            const float* __restrict__ bih, const float* __restrict__ bhh,
                            const float* __restrict__ wfc, const float* __restrict__ ufc)
{
    __shared__ float tv[HID];
    __shared__ float red[512];
    __shared__ float nrm;
    __shared__ float inv_s[4];
    int tid = threadIdx.x;

    // ---- ih: W [512,33] ----
    if (tid < CIN) {
        float s = 0.f;
        for (int g = 0; g < GATES; g++) s += wih[g * CIN + tid] * uih[g];
        tv[tid] = s;
    }
    __syncthreads();
    if (tid == 0) {
        float n = 0.f;
        for (int c = 0; c < CIN; c++) n += tv[c] * tv[c];
        nrm = sqrtf(n) + EPSF;
    }
    __syncthreads();
    {
        float a = 0.f;
        for (int c = 0; c < CIN; c++) a += wih[tid * CIN + c] * tv[c];
        a /= nrm;
        red[tid] = a * a;
    }
    __syncthreads();
    for (int off = 256; off; off >>= 1) {
        if (tid < off) red[tid] += red[tid + off];
        __syncthreads();
    }
    if (tid == 0) {
        float ssum = red[0];                      // ||W v||^2
        float v = (sqrtf(ssum) + EPSF) / ssum;    // 1/sigma
        g_inv_arr[0] = v; inv_s[0] = v;
    }
    __syncthreads();

    // ---- hh: W [512,128] ----
    if (tid < HID) {
        float s = 0.f;
        for (int g = 0; g < GATES; g++) s += whh[g * HID + tid] * uhh[g];
        tv[tid] = s;
    }
    __syncthreads();
    if (tid == 0) {
        float n = 0.f;
        for (int k = 0; k < HID; k++) n += tv[k] * tv[k];
        nrm = sqrtf(n) + EPSF;
    }
    __syncthreads();
    {
        float a = 0.f;
        for (int k = 0; k < HID; k++) a += whh[tid * HID + k] * tv[k];
        a /= nrm;
        red[tid] = a * a;
    }
    __syncthreads();
    for (int off = 256; off; off >>= 1) {
        if (tid < off) red[tid] += red[tid + off];
        __syncthreads();
    }
    if (tid == 0) {
        float ssum = red[0];
        float v = (sqrtf(ssum) + EPSF) / ssum;
        g_inv_arr[1] = v; inv_s[1] = v;
    }
    __syncthreads();

    // ---- fc: W [1,128] ----
    red[tid] = (tid < HID) ? wfc[tid] * wfc[tid] : 0.f;
    __syncthreads();
    for (int off = 256; off; off >>= 1) {
        if (tid < off) red[tid] += red[tid + off];
        __syncthreads();
    }
    if (tid == 0) {
        float wn2 = red[0];
        float u0  = ufc[0];
        float tn  = fabsf(u0) * sqrtf(wn2) + EPSF;   // ||W^T u||
        float s   = u0 * wn2 / tn;                   // W @ v (scalar)
        float sig = s * s / (fabsf(s) + EPSF);
        float v = 1.f / sig;
        g_inv_arr[2] = v; inv_s[2] = v;
    }
    __syncthreads();

    // ---- scale + pack ----
    float i0 = inv_s[0], i1 = inv_s[1];
    // Wih transposed & scaled: g_wt[c*512+g]
    for (int c = 0; c < CIN; c++)
        g_wt[c * GATES + tid] = wih[tid * CIN + c] * i0;
    g_bias[tid] = bih[tid] + bhh[tid];

    int gp = tid >> 1, s = tid & 1;
    // reg half: k2 0..7, f32 pairs, gate-paired
    for (int k2 = 0; k2 < KREG2; k2++) {
        float we = whh[tid * HID + 2 * k2]     * i1;
        float wo = whh[tid * HID + 2 * k2 + 1] * i1;
        ((ull_t*)g_whh_r)[(k2 * 256 + gp) * 2 + s] = pack2(we, wo);
    }
    // smem half: k4 0..27 (global k 16..127), bf16 pairs, gate-paired
    for (int k4 = 0; k4 < K4SM; k4++) {
        int k2a = KREG2 + 2 * k4, k2b = k2a + 1;
        u32_t pa = pack_bf2(whh[tid * HID + 2 * k2a] * i1,
                            whh[tid * HID + 2 * k2a + 1] * i1);
        u32_t pb = pack_bf2(whh[tid * HID + 2 * k2b] * i1,
                            whh[tid * HID + 2 * k2b + 1] * i1);
        ((u32_t*)g_whh_s)[(k4 * 256 + gp) * 4 + s]     = pa;
        ((u32_t*)g_whh_s)[(k4 * 256 + gp) * 4 + 2 + s] = pb;
    }
}

// ---------------------------------------------------------------------------
// Kernel C: gates_x = x_aug @ Wih_n^T + bias (f32x2 packed over gate pairs).
// grid = 8192 blocks x 32 rows, 256 threads; thread t owns gates (2t, 2t+1).
// ---------------------------------------------------------------------------
__global__ void gates_kernel(const float* __restrict__ x)
{
    __shared__ ull_t xs_d[CIN * 34];   // x duplicated (v,v), [c][34 rows]
    int row0 = blockIdx.x * 32;
    int tid  = threadIdx.x;

    for (int i = tid; i < 32 * CHAN; i += 256) {
        int r = i >> 5, c = i & 31;
        xs_d[c * 34 + r] = pack_dup(x[(size_t)(row0 + r) * CHAN + c]);
    }
    if (tid < 32)
        xs_d[CHAN * 34 + tid] = pack_dup(g_std_arr[(row0 + tid) & (T_STEPS - 1)]);
    __syncthreads();

    const ull_t* wt2   = (const ull_t*)g_wt;     // (w_2t, w_2t+1) f32 pairs
    const ull_t* bias2 = (const ull_t*)g_bias;
    ull_t*       gout  = (ull_t*)g_gates;
    ull_t bp = bias2[tid];

    for (int rb = 0; rb < 32; rb += 8) {
        ull_t acc[8];
        #pragma unroll
        for (int r = 0; r < 8; r++) acc[r] = bp;
        #pragma unroll
        for (int c = 0; c < CIN; c++) {
            ull_t w = wt2[c * (GATES / 2) + tid];
            #pragma unroll
            for (int r = 0; r < 8; r++)
                ffma2(acc[r], w, xs_d[c * 34 + rb + r]);
        }
        #pragma unroll
        for (int r = 0; r < 8; r++)
            gout[(size_t)(row0 + rb + r) * (GATES / 2) + tid] = acc[r];
    }
}

// ---------------------------------------------------------------------------
// Kernel D: persistent LSTM + online-softmax attention + FC epilogue.
// 128 blocks x 4 batch rows, 512 threads (4 warps/SMSP), 512 steps.
// Lane-pair sharing: gp = tid>>1 owns gates (2gp, 2gp+1); rh = tid&1 picks
// rows (2rh, 2rh+1). Weight LDS wavefronts carry 16 distinct addrs (half
// crossbar); h rows padded to 132 floats (conflict-free dual-row LDS.128).
// Hybrid weights: k 0..15 f32 in 32 regs (no unpack), k 16..127 bf16 smem.
// Pointwise 1 slot/thread; softmax state in regs; two barriers/step.
// ---------------------------------------------------------------------------
__global__ void __launch_bounds__(512, 1)
lstm_kernel(const float* __restrict__ attn_w,
            const float* __restrict__ fc_w,
            const float* __restrict__ fc_b,
            float* __restrict__ out)
{
    extern __shared__ __align__(16) unsigned char smem_raw[];
    ulonglong2* wsm2 = (ulonglong2*)smem_raw;      // [28 k4][256 gp] bf16 4-pack

    __shared__ __align__(16) float h_s[4 * HPAD];  // [4][132] padded
    __shared__ float gts[4 * GATES];               // [4][512]
    __shared__ float aw_s[HID];
    __shared__ float fw_s[HID];
    __shared__ float lpart[16];                    // per-warp attn partials

    int tid  = threadIdx.x;
    int b0   = blockIdx.x * 4;
    int wid  = tid >> 5, lane = tid & 31;
    int gp   = tid >> 1;          // gate-pair index (0..255)
    int rh   = tid & 1;           // row-half: rows 2rh, 2rh+1
    int rA   = 2 * rh, rB = 2 * rh + 1;
    int r0   = tid >> 7;          // pointwise row (0..3)
    int j0   = tid & 127;         // pointwise hidden index

    // weights: k2 0..7 into 8 ulonglong2 = 32 regs ({wE, wO} f32 pairs)
    ulonglong2 wr[KREG2];
    #pragma unroll
    for (int k2 = 0; k2 < KREG2; k2++)
        wr[k2] = g_whh_r[k2 * 256 + gp];
    // stage bf16 half into smem
    for (int i = tid; i < K4SM * 256; i += 512)
        wsm2[i] = g_whh_s[i];

    for (int i = tid; i < 4 * HPAD; i += 512) h_s[i] = 0.f;
    if (tid < HID) { aw_s[tid] = attn_w[tid]; fw_s[tid] = fc_w[tid]; }
    __syncthreads();

    float cst  = 0.f;          // cell state for slot (r0, j0)
    float accp = 0.f;          // online pooled accumulator
    float mloc = -INFINITY;    // softmax running max (redundant per row-thread)
    float sloc = 0.f;          // softmax running sum

    const float4* h4   = (const float4*)h_s;       // row stride HPAD/4 = 33
    const ull_t*  gsrc = (const ull_t*)g_gates;    // gate-pair view [.][256]
    ull_t*        gts2 = (ull_t*)gts;              // [4][256] ull

    for (int t = 0; t < T_STEPS; t++) {
        // prefetch gates_x pairs for both rows (coalesced)
        ull_t gxA = gsrc[((size_t)(b0 + rA) * T_STEPS + t) * 256 + gp];
        ull_t gxB = gsrc[((size_t)(b0 + rB) * T_STEPS + t) * 256 + gp];

        // gates += h @ Whh^T  (acc = (sum_even_k, sum_odd_k); E/O = gate pair)
        ull_t aE0 = 0, aO0 = 0, aE1 = 0, aO1 = 0;
        #pragma unroll
        for (int k4 = 0; k4 < KREG2 / 2; k4++) {   // register half (no unpack)
            float4 hA = h4[rA * (HPAD / 4) + k4];  // LDS.128, 2 addrs, no conflict
            float4 hB = h4[rB * (HPAD / 4) + k4];
            ull_t hA01 = pack2(hA.x, hA.y), hA23 = pack2(hA.z, hA.w);
            ull_t hB01 = pack2(hB.x, hB.y), hB23 = pack2(hB.z, hB.w);
            ffma2(aE0, wr[2 * k4].x, hA01); ffma2(aO0, wr[2 * k4].y, hA01);
            ffma2(aE1, wr[2 * k4].x, hB01); ffma2(aO1, wr[2 * k4].y, hB01);
            ffma2(aE0, wr[2 * k4 + 1].x, hA23); ffma2(aO0, wr[2 * k4 + 1].y, hA23);
            ffma2(aE1, wr[2 * k4 + 1].x, hB23); ffma2(aO1, wr[2 * k4 + 1].y, hB23);
        }
        #pragma unroll 7
        for (int k4 = KREG2 / 2; k4 < HID / 4; k4++) {  // bf16 smem half
            ulonglong2 wp = wsm2[(k4 - KREG2 / 2) * 256 + gp];  // 16-addr LDS.128
            float2 wa = unpack2(wp.x);   // (pairE_a, pairO_a) as raw u32 in f32
            float2 wb = unpack2(wp.y);
            ull_t wEa = bf2_to_f32x2(__float_as_uint(wa.x));
            ull_t wOa = bf2_to_f32x2(__float_as_uint(wa.y));
            ull_t wEb = bf2_to_f32x2(__float_as_uint(wb.x));
            ull_t wOb = bf2_to_f32x2(__float_as_uint(wb.y));
            float4 hA = h4[rA * (HPAD / 4) + k4];
            float4 hB = h4[rB * (HPAD / 4) + k4];
            ull_t hA01 = pack2(hA.x, hA.y), hA23 = pack2(hA.z, hA.w);
            ull_t hB01 = pack2(hB.x, hB.y), hB23 = pack2(hB.z, hB.w);
            ffma2(aE0, wEa, hA01); ffma2(aO0, wOa, hA01);
            ffma2(aE1, wEa, hB01); ffma2(aO1, wOa, hB01);
            ffma2(aE0, wEb, hA23); ffma2(aO0, wOb, hA23);
            ffma2(aE1, wEb, hB23); ffma2(aO1, wOb, hB23);
        }
        {
            float2 ga = unpack2(gxA), gb = unpack2(gxB);
            gts2[rA * 256 + gp] = pack2(hsum2(aE0) + ga.x, hsum2(aO0) + ga.y);
            gts2[rB * 256 + gp] = pack2(hsum2(aE1) + gb.x, hsum2(aO1) + gb.y);
        }
        __syncthreads();                            // sync1: gates ready

        // pointwise LSTM cell (1 slot/thread); exp-based activations
        const float* gr = &gts[r0 * GATES];
        float gi = gr[j0], gf = gr[HID + j0];
        float gg = gr[2 * HID + j0], go = gr[3 * HID + j0];
        float iv = 1.f / (1.f + __expf(-gi));
        float fv = 1.f / (1.f + __expf(-gf));
        float gv = 2.f / (1.f + __expf(-2.f * gg)) - 1.f;   // tanh
        float ov = 1.f / (1.f + __expf(-go));
        float c  = fv * cst + iv * gv;
        cst      = c;
        float hv = ov * (2.f / (1.f + __expf(-2.f * c)) - 1.f);
        h_s[r0 * HPAD + j0] = hv;

        // attention partial: per-warp shuffle reduce of h*aw
        float part = hv * aw_s[j0];
        #pragma unroll
        for (int off = 16; off; off >>= 1)
            part += __shfl_xor_sync(0xffffffffu, part, off);
        if (lane == 0) lpart[wid] = part;
        __syncthreads();                            // sync2: h + partials ready

        // online softmax, state in registers (redundant across a row's threads)
        float l = lpart[r0 * 4] + lpart[r0 * 4 + 1]
                + lpart[r0 * 4 + 2] + lpart[r0 * 4 + 3];
        float mnew = fmaxf(mloc, l);
        float al   = __expf(mloc - mnew);           // 0 on first step
        float pv   = __expf(l - mnew);
        mloc = mnew;
        sloc = sloc * al + pv;
        accp = accp * al + pv * hv;
        // hazards: h_s written pre-sync2, read by matvec(t+1) post-sync2 ✓;
        // gts read pre-sync2, rewritten post-sync2 ✓; lpart read here post-
        // sync2, next written post-sync1(t+1) ✓. Two barriers/step suffice.
    }

    // epilogue: pooled = acc/s ; score = pooled . (fc_w/sigma) + fc_b
    __syncthreads();                                // lpart reads done, reuse
    float po   = accp / sloc;
    float part = po * fw_s[j0];
    #pragma unroll
    for (int off = 16; off; off >>= 1)
        part += __shfl_xor_sync(0xffffffffu, part, off);
    if (lane == 0) lpart[wid] = part;
    __syncthreads();
    if (tid < 4) {
        float sc = lpart[tid * 4] + lpart[tid * 4 + 1]
                 + lpart[tid * 4 + 2] + lpart[tid * 4 + 3];
        out[b0 + tid] = sc * g_inv_arr[2] + fc_b[0];
    }
}

// ---------------------------------------------------------------------------
extern "C" void kernel_launch(void* const* d_in, const int* in_sizes, int n_in,
                              void* d_out, int out_size)
{
    const float* x      = (const float*)d_in[0];
    const float* w_ih   = (const float*)d_in[1];
    const float* u_ih   = (const float*)d_in[2];
    const float* w_hh   = (const float*)d_in[3];
    const float* u_hh   = (const float*)d_in[4];
    const float* b_ih   = (const float*)d_in[5];
    const float* b_hh   = (const float*)d_in[6];
    const float* attn_w = (const float*)d_in[7];
    // d_in[8] = attn_b (softmax shift-invariant, unused)
    const float* fc_w   = (const float*)d_in[9];
    const float* u_fc   = (const float*)d_in[10];
    const float* fc_b   = (const float*)d_in[11];
    float* out = (float*)d_out;

    std_kernel<<<T_STEPS, 256>>>(x);
    prep_kernel<<<1, 512>>>(w_ih, u_ih, w_hh, u_hh, b_ih, b_hh, fc_w, u_fc);
    gates_kernel<<<(BATCH * T_STEPS) / 32, 256>>>(x);

    int smem = K4SM * 256 * 16;   // 112 KB dynamic: bf16 weight half
    cudaFuncSetAttribute(lstm_kernel, cudaFuncAttributeMaxDynamicSharedMemorySize, smem);
    lstm_kernel<<<BATCH / 4, 512, smem>>>(attn_w, fc_w, fc_b, out);
}

// round 17
// speedup vs baseline: 1.7411x; 1.4717x over previous
#include <cuda_runtime.h>
#include <cuda_bf16.h>
#include <math.h>

#define BATCH   512
#define T_STEPS 512
#define CHAN    32
#define CIN     33
#define HID     128
#define GATES   512   // 4*H
#define EPSF    1e-12f

#define HROW    136   // hbf row stride in bf16 elems (272 B = 17*16, conflict-free)

typedef unsigned long long ull_t;
typedef unsigned int u32_t;

// ---------------------------------------------------------------------------
// helpers
// ---------------------------------------------------------------------------
__device__ __forceinline__ void ffma2(ull_t& d, ull_t a, ull_t b) {
    asm("fma.rn.f32x2 %0, %1, %2, %0;" : "+l"(d) : "l"(a), "l"(b));
}
__device__ __forceinline__ ull_t pack_dup(float v) {
    ull_t r; u32_t b = __float_as_uint(v);
    asm("mov.b64 %0, {%1, %1};" : "=l"(r) : "r"(b));
    return r;
}
__device__ __forceinline__ ull_t pack2(float a, float b) {
    ull_t r;
    asm("mov.b64 %0, {%1, %2};" : "=l"(r)
        : "r"(__float_as_uint(a)), "r"(__float_as_uint(b)));
    return r;
}
// mma.sync m16n8k16 row.col f32.bf16.bf16.f32
__device__ __forceinline__ void mma16816(float& c0, float& c1, float& c2, float& c3,
                                         u32_t a0, u32_t a1, u32_t a2, u32_t a3,
                                         u32_t b0, u32_t b1) {
    asm("mma.sync.aligned.m16n8k16.row.col.f32.bf16.bf16.f32 "
        "{%0,%1,%2,%3}, {%4,%5,%6,%7}, {%8,%9}, {%0,%1,%2,%3};"
        : "+f"(c0), "+f"(c1), "+f"(c2), "+f"(c3)
        : "r"(a0), "r"(a1), "r"(a2), "r"(a3), "r"(b0), "r"(b1));
}
__device__ __forceinline__ void ldmatrix_x4(u32_t& r0, u32_t& r1, u32_t& r2, u32_t& r3,
                                            u32_t addr) {
    asm volatile("ldmatrix.sync.aligned.m8n8.x4.shared.b16 {%0,%1,%2,%3}, [%4];"
                 : "=r"(r0), "=r"(r1), "=r"(r2), "=r"(r3) : "r"(addr));
}

// ---------------------------------------------------------------------------
// Device scratch (static; allocations are forbidden)
// ---------------------------------------------------------------------------
__device__ float          g_std_arr[T_STEPS];       // minibatch-std scalar per t
__device__ float          g_inv_arr[4];             // 1/sigma: ih, hh, fc
__device__ float          g_wt[CIN * GATES];        // Wih^T scaled: [33][512]
__device__ float          g_bias[GATES];            // b_ih + b_hh
__device__ __nv_bfloat16  g_whh_bf[GATES * HID];    // Whh scaled, bf16 [512][128]
__device__ float          g_gates[(size_t)BATCH * T_STEPS * GATES]; // 536 MB

// ---------------------------------------------------------------------------
// Kernel A: minibatch std feature. grid=T, block=256 (8 b-seg x 32 chan)
// ---------------------------------------------------------------------------
__global__ void std_kernel(const float* __restrict__ x)
{
    int t   = blockIdx.x;
    int tid = threadIdx.x;
    int c   = tid & 31;
    int seg = tid >> 5;

    float s = 0.f, ss = 0.f;
    for (int b = seg; b < BATCH; b += 8) {
        float v = x[((size_t)b * T_STEPS + t) * CHAN + c];
        s  += v;
        ss += v * v;
    }
    __shared__ float sm1[256], sm2[256];
    sm1[tid] = s; sm2[tid] = ss;
    __syncthreads();
    if (seg == 0) {
        for (int k = 1; k < 8; k++) { s += sm1[k * 32 + c]; ss += sm2[k * 32 + c]; }
        float mean = s * (1.f / 512.f);
        float var  = (ss - 512.f * mean * mean) * (1.f / 511.f);
        float sd   = sqrtf(fmaxf(var, 0.f));
        #pragma unroll
        for (int off = 16; off; off >>= 1)
            sd += __shfl_xor_sync(0xffffffffu, sd, off);
        if (c == 0) g_std_arr[t] = sd * (1.f / 32.f);
    }
}

// ---------------------------------------------------------------------------
// Kernel B: spectral norms (one power iteration, matching reference exactly)
// then scale+transpose Wih, combine bias, quantize Whh to bf16 row-major.
// single block, 512 threads (tid = gate)
// ---------------------------------------------------------------------------
__global__ void prep_kernel(const float* __restrict__ wih, const float* __restrict__ uih,
                            const float* __restrict__ whh, const float* __restrict__ uhh,
                            const float* __restrict__ bih, const float* __restrict__ bhh,
                            const float* __restrict__ wfc, const float* __restrict__ ufc)
{
    __shared__ float tv[HID];
    __shared__ float red[512];
    __shared__ float nrm;
    __shared__ float inv_s[4];
    int tid = threadIdx.x;

    // ---- ih: W [512,33] ----
    if (tid < CIN) {
        float s = 0.f;
        for (int g = 0; g < GATES; g++) s += wih[g * CIN + tid] * uih[g];
        tv[tid] = s;
    }
    __syncthreads();
    if (tid == 0) {
        float n = 0.f;
        for (int c = 0; c < CIN; c++) n += tv[c] * tv[c];
        nrm = sqrtf(n) + EPSF;
    }
    __syncthreads();
    {
        float a = 0.f;
        for (int c = 0; c < CIN; c++) a += wih[tid * CIN + c] * tv[c];
        a /= nrm;
        red[tid] = a * a;
    }
    __syncthreads();
    for (int off = 256; off; off >>= 1) {
        if (tid < off) red[tid] += red[tid + off];
        __syncthreads();
    }
    if (tid == 0) {
        float ssum = red[0];                      // ||W v||^2
        float v = (sqrtf(ssum) + EPSF) / ssum;    // 1/sigma
        g_inv_arr[0] = v; inv_s[0] = v;
    }
    __syncthreads();

    // ---- hh: W [512,128] ----
    if (tid < HID) {
        float s = 0.f;
        for (int g = 0; g < GATES; g++) s += whh[g * HID + tid] * uhh[g];
        tv[tid] = s;
    }
    __syncthreads();
    if (tid == 0) {
        float n = 0.f;
        for (int k = 0; k < HID; k++) n += tv[k] * tv[k];
        nrm = sqrtf(n) + EPSF;
    }
    __syncthreads();
    {
        float a = 0.f;
        for (int k = 0; k < HID; k++) a += whh[tid * HID + k] * tv[k];
        a /= nrm;
        red[tid] = a * a;
    }
    __syncthreads();
    for (int off = 256; off; off >>= 1) {
        if (tid < off) red[tid] += red[tid + off];
        __syncthreads();
    }
    if (tid == 0) {
        float ssum = red[0];
        float v = (sqrtf(ssum) + EPSF) / ssum;
        g_inv_arr[1] = v; inv_s[1] = v;
    }
    __syncthreads();

    // ---- fc: W [1,128] ----
    red[tid] = (tid < HID) ? wfc[tid] * wfc[tid] : 0.f;
    __syncthreads();
    for (int off = 256; off; off >>= 1) {
        if (tid < off) red[tid] += red[tid + off];
        __syncthreads();
    }
    if (tid == 0) {
        float wn2 = red[0];
        float u0  = ufc[0];
        float tn  = fabsf(u0) * sqrtf(wn2) + EPSF;   // ||W^T u||
        float s   = u0 * wn2 / tn;                   // W @ v (scalar)
        float sig = s * s / (fabsf(s) + EPSF);
        float v = 1.f / sig;
        g_inv_arr[2] = v; inv_s[2] = v;
    }
    __syncthreads();

    // ---- scale + pack ----
    float i0 = inv_s[0], i1 = inv_s[1];
    for (int c = 0; c < CIN; c++)
        g_wt[c * GATES + tid] = wih[tid * CIN + c] * i0;
    g_bias[tid] = bih[tid] + bhh[tid];
    // Whh scaled -> bf16, row-major [gate][k]
    for (int k = 0; k < HID; k++)
        g_whh_bf[tid * HID + k] = __float2bfloat16(whh[tid * HID + k] * i1);
}

// ---------------------------------------------------------------------------
// Kernel C: gates_x = x_aug @ Wih_n^T + bias (f32x2 packed over gate pairs).
// grid = 8192 blocks x 32 rows, 256 threads; thread t owns gates (2t, 2t+1).
// ---------------------------------------------------------------------------
__global__ void gates_kernel(const float* __restrict__ x)
{
    __shared__ ull_t xs_d[CIN * 34];   // x duplicated (v,v), [c][34 rows]
    int row0 = blockIdx.x * 32;
    int tid  = threadIdx.x;

    for (int i = tid; i < 32 * CHAN; i += 256) {
        int r = i >> 5, c = i & 31;
        xs_d[c * 34 + r] = pack_dup(x[(size_t)(row0 + r) * CHAN + c]);
    }
    if (tid < 32)
        xs_d[CHAN * 34 + tid] = pack_dup(g_std_arr[(row0 + tid) & (T_STEPS - 1)]);
    __syncthreads();

    const ull_t* wt2   = (const ull_t*)g_wt;
    const ull_t* bias2 = (const ull_t*)g_bias;
    ull_t*       gout  = (ull_t*)g_gates;
    ull_t bp = bias2[tid];

    for (int rb = 0; rb < 32; rb += 8) {
        ull_t acc[8];
        #pragma unroll
        for (int r = 0; r < 8; r++) acc[r] = bp;
        #pragma unroll
        for (int c = 0; c < CIN; c++) {
            ull_t w = wt2[c * (GATES / 2) + tid];
            #pragma unroll
            for (int r = 0; r < 8; r++)
                ffma2(acc[r], w, xs_d[c * 34 + rb + r]);
        }
        #pragma unroll
        for (int r = 0; r < 8; r++)
            gout[(size_t)(row0 + rb + r) * (GATES / 2) + tid] = acc[r];
    }
}

// ---------------------------------------------------------------------------
// Kernel D: persistent LSTM via TENSOR CORES (mma.m16n8k16 bf16) +
// online-softmax attention + FC epilogue.
// 128 blocks x 4 batch rows, 512 threads (16 warps), 512 steps.
// A = h padded to 16x128 bf16 in smem (rows 4..15 zero), read via ldmatrix.
// B = Whh^T in REGISTERS (64 u32/thread, loaded once; zero loop traffic).
// Warp w owns gates [32w, 32w+32): 4 n-tiles x 8 k-chunks = 32 HMMA/step.
// Pointwise 1 slot/thread; softmax state in regs; two barriers/step.
// ---------------------------------------------------------------------------
__global__ void __launch_bounds__(512, 1)
lstm_kernel(const float* __restrict__ attn_w,
            const float* __restrict__ fc_w,
            const float* __restrict__ fc_b,
            float* __restrict__ out)
{
    __shared__ __align__(16) __nv_bfloat16 hbf[16 * HROW];  // A: [16][136] bf16
    __shared__ float gts[4 * GATES];                        // [4][512]
    __shared__ float aw_s[HID];
    __shared__ float fw_s[HID];
    __shared__ float lpart[16];                             // per-warp attn partials

    int tid   = threadIdx.x;
    int b0    = blockIdx.x * 4;
    int wid   = tid >> 5, lane = tid & 31;
    int gbase = wid * 32;          // this warp's 32 gates
    int r0    = tid >> 7;          // pointwise row (0..3)
    int j0    = tid & 127;         // pointwise hidden index

    // ---- B fragments into registers (once): [4 nt][8 kc] x 2 u32 = 64 regs ----
    // b0: Whh[g][k0..k0+1], b1: Whh[g][k0+8..k0+9]; g = gbase+nt*8+lane/4,
    // k0 = kc*16+(lane%4)*2   (mma B col-major fragment layout)
    u32_t b0r[4][8], b1r[4][8];
    {
        int g  = gbase + (lane >> 2);          // + nt*8 added below
        int k0 = (lane & 3) * 2;               // + kc*16 below
        #pragma unroll
        for (int nt = 0; nt < 4; nt++)
            #pragma unroll
            for (int kc = 0; kc < 8; kc++) {
                const __nv_bfloat16* p = &g_whh_bf[(g + nt * 8) * HID + kc * 16 + k0];
                b0r[nt][kc] = *(const u32_t*)p;
                b1r[nt][kc] = *(const u32_t*)(p + 8);
            }
    }

    // zero A buffer (rows 4..15 stay zero forever)
    for (int i = tid; i < 16 * HROW; i += 512) hbf[i] = __float2bfloat16(0.f);
    if (tid < HID) { aw_s[tid] = attn_w[tid]; fw_s[tid] = fc_w[tid]; }
    __syncthreads();

    // ldmatrix source address (fixed per lane, kc-offset added in loop):
    // tile row = lane&15, col-half = lane>>4
    u32_t abase;
    {
        const __nv_bfloat16* ap = &hbf[(lane & 15) * HROW + (lane >> 4) * 8];
        abase = (u32_t)__cvta_generic_to_shared(ap);
    }

    float cst  = 0.f;          // cell state for slot (r0, j0)
    float accp = 0.f;          // online pooled accumulator
    float mloc = -INFINITY;    // softmax running max
    float sloc = 0.f;          // softmax running sum

    const float* gsrc = g_gates;

    for (int t = 0; t < T_STEPS; t++) {
        // prefetch gates_x pairs (lanes 0..15 own output rows 0..3)
        float2 gx[4];
        int orow = lane >> 2;                   // 0..3 for lanes<16
        int ocol = (lane & 3) * 2;
        if (lane < 16) {
            #pragma unroll
            for (int nt = 0; nt < 4; nt++)
                gx[nt] = *(const float2*)&gsrc[((size_t)(b0 + orow) * T_STEPS + t)
                                               * GATES + gbase + nt * 8 + ocol];
        }

        // ---- tensor-core matvec: gates_hh = h @ Whh^T ----
        float c0[4] = {0.f, 0.f, 0.f, 0.f};
        float c1[4] = {0.f, 0.f, 0.f, 0.f};
        float c2[4] = {0.f, 0.f, 0.f, 0.f};
        float c3[4] = {0.f, 0.f, 0.f, 0.f};
        #pragma unroll
        for (int kc = 0; kc < 8; kc++) {
            u32_t a0, a1, a2, a3;
            ldmatrix_x4(a0, a1, a2, a3, abase + kc * 32);
            #pragma unroll
            for (int nt = 0; nt < 4; nt++)
                mma16816(c0[nt], c1[nt], c2[nt], c3[nt],
                         a0, a1, a2, a3, b0r[nt][kc], b1r[nt][kc]);
        }

        // epilogue: lanes 0..15 hold valid rows 0..3 in (c0, c1)
        if (lane < 16) {
            #pragma unroll
            for (int nt = 0; nt < 4; nt++) {
                int g0 = gbase + nt * 8 + ocol;
                *(ull_t*)&gts[orow * GATES + g0] =
                    pack2(c0[nt] + gx[nt].x, c1[nt] + gx[nt].y);   // STS.64
            }
        }
        __syncthreads();                            // sync1: gates ready

        // pointwise LSTM cell (1 slot/thread); exp-based activations
        const float* gr = &gts[r0 * GATES];
        float gi = gr[j0], gf = gr[HID + j0];
        float gg = gr[2 * HID + j0], go = gr[3 * HID + j0];
        float iv = 1.f / (1.f + __expf(-gi));
        float fv = 1.f / (1.f + __expf(-gf));
        float gv = 2.f / (1.f + __expf(-2.f * gg)) - 1.f;   // tanh
        float ov = 1.f / (1.f + __expf(-go));
        float c  = fv * cst + iv * gv;
        cst      = c;
        float hv = ov * (2.f / (1.f + __expf(-2.f * c)) - 1.f);
        hbf[r0 * HROW + j0] = __float2bfloat16(hv);         // bf16 h for mma

        // attention partial: per-warp shuffle reduce of h*aw
        float part = hv * aw_s[j0];
        #pragma unroll
        for (int off = 16; off; off >>= 1)
            part += __shfl_xor_sync(0xffffffffu, part, off);
        if (lane == 0) lpart[wid] = part;
        __syncthreads();                            // sync2: h + partials ready

        // online softmax, state in registers (redundant across a row's threads)
        float l = lpart[r0 * 4] + lpart[r0 * 4 + 1]
                + lpart[r0 * 4 + 2] + lpart[r0 * 4 + 3];
        float mnew = fmaxf(mloc, l);
        float al   = __expf(mloc - mnew);           // 0 on first step
        float pv   = __expf(l - mnew);
        mloc = mnew;
        sloc = sloc * al + pv;
        accp = accp * al + pv * hv;
        // hazards: hbf reads (ldmatrix, t+1) happen pre-sync1(t+1), writes of
        // h_{t+1} post-sync1(t+1) — reads of h_t complete before sync1(t) ✓;
        // gts written pre-sync1, read post-sync1 ✓; lpart read post-sync2,
        // next written post-sync1(t+1) ✓. Two barriers/step suffice.
    }

    // epilogue: pooled = acc/s ; score = pooled . (fc_w/sigma) + fc_b
    __syncthreads();                                // lpart reads done, reuse
    float po   = accp / sloc;
    float part = po * fw_s[j0];
    #pragma unroll
    for (int off = 16; off; off >>= 1)
        part += __shfl_xor_sync(0xffffffffu, part, off);
    if (lane == 0) lpart[wid] = part;
    __syncthreads();
    if (tid < 4) {
        float sc = lpart[tid * 4] + lpart[tid * 4 + 1]
                 + lpart[tid * 4 + 2] + lpart[tid * 4 + 3];
        out[b0 + tid] = sc * g_inv_arr[2] + fc_b[0];
    }
}

// ---------------------------------------------------------------------------
extern "C" void kernel_launch(void* const* d_in, const int* in_sizes, int n_in,
                              void* d_out, int out_size)
{
    const float* x      = (const float*)d_in[0];
    const float* w_ih   = (const float*)d_in[1];
    const float* u_ih   = (const float*)d_in[2];
    const float* w_hh   = (const float*)d_in[3];
    const float* u_hh   = (const float*)d_in[4];
    const float* b_ih   = (const float*)d_in[5];
    const float* b_hh   = (const float*)d_in[6];
    const float* attn_w = (const float*)d_in[7];
    // d_in[8] = attn_b (softmax shift-invariant, unused)
    const float* fc_w   = (const float*)d_in[9];
    const float* u_fc   = (const float*)d_in[10];
    const float* fc_b   = (const float*)d_in[11];
    float* out = (float*)d_out;

    std_kernel<<<T_STEPS, 256>>>(x);
    prep_kernel<<<1, 512>>>(w_ih, u_ih, w_hh, u_hh, b_ih, b_hh, fc_w, u_fc);
    gates_kernel<<<(BATCH * T_STEPS) / 32, 256>>>(x);
    lstm_kernel<<<BATCH / 4, 512>>>(attn_w, fc_w, fc_b, out);
}